// round 1
// baseline (speedup 1.0000x reference)
#include <cuda_runtime.h>
#include <cuda_bf16.h>
#include <math.h>

// ---------------- problem constants ----------------
#define NB    8      // batch
#define DD    256    // vec dim
#define HEADS 8
#define PN    3136   // patches (56x56)
#define CH    56
#define WS    7
#define P     49
#define NH    8      // windows per side
#define WIN   64
#define HD    2048   // HEADS*DD
#define PIX   224

#define BATCH_X   (DD*PN)          // 802816
#define BATCH_QKV ((long)HD*PN)    // 6422528

// ---------------- static scratch -------------------
__device__ float g_xs[(long)NB * DD * PN];          // shifted input  25.7MB
__device__ float g_qkv[3L * HD * PN];               // per-batch K,Q,V  77MB
__device__ float g_att[(long)NB * HD * PN];         // attention out  205MB

// ---------------- shift kernel ---------------------
__global__ void shift_kernel(const float* __restrict__ in, float* __restrict__ out) {
    long idx = (long)blockIdx.x * blockDim.x + threadIdx.x;
    if (idx >= (long)NB * DD * PN) return;
    int p = (int)(idx % PN);
    int d = (int)((idx / PN) % DD);
    int n = (int)(idx / ((long)DD * PN));
    int c  = d >> 4;
    int py = (d >> 2) & 3;
    int px = d & 3;
    int i = p / CH, j = p % CH;
    int r = i * 4 + py, s = j * 4 + px;
    int rs = (r + PIX - 3) % PIX;
    int ss = (s + PIX - 3) % PIX;
    int ip = rs >> 2, pyp = rs & 3;
    int jp = ss >> 2, pxp = ss & 3;
    int dp = (c << 4) + (pyp << 2) + pxp;
    int pp = ip * CH + jp;
    out[idx] = in[((long)n * DD + dp) * PN + pp];
}

// ---------------- sgemm tile (128x128x8, 256 thr) ---
__device__ __forceinline__ void gemm_tile(
    const float* __restrict__ A,   // [M,K] row-major
    const float* __restrict__ B,   // [K,Nn] row-major
    const float* __restrict__ bias,// [M]
    float* __restrict__ C,         // [M,Nn]
    int M, int Nn, int K)
{
    __shared__ float As[8][128];
    __shared__ float Bs[8][128];

    int tid  = threadIdx.x;
    int row0 = blockIdx.y * 128;
    int col0 = blockIdx.x * 128;

    int aRow = tid >> 1;
    int aCol = (tid & 1) << 2;
    int bRow = tid >> 5;
    int bCol = (tid & 31) << 2;
    int tx = tid & 15, ty = tid >> 4;

    const float* Aptr = A + (long)(row0 + aRow) * K + aCol;
    const float* Bptr = B + (long)bRow * Nn + col0 + bCol;
    bool bvalid = (col0 + bCol) < Nn;

    float acc[8][8];
#pragma unroll
    for (int i = 0; i < 8; i++)
#pragma unroll
        for (int j = 0; j < 8; j++) acc[i][j] = 0.f;

    for (int k0 = 0; k0 < K; k0 += 8) {
        float4 av = *(const float4*)(Aptr + k0);
        float4 bv = bvalid ? *(const float4*)(Bptr + (long)k0 * Nn)
                           : make_float4(0.f, 0.f, 0.f, 0.f);
        As[aCol + 0][aRow] = av.x;
        As[aCol + 1][aRow] = av.y;
        As[aCol + 2][aRow] = av.z;
        As[aCol + 3][aRow] = av.w;
        *(float4*)&Bs[bRow][bCol] = bv;
        __syncthreads();
#pragma unroll
        for (int kk = 0; kk < 8; kk++) {
            float a[8], b[8];
            *(float4*)&a[0] = *(const float4*)&As[kk][ty * 4];
            *(float4*)&a[4] = *(const float4*)&As[kk][64 + ty * 4];
            *(float4*)&b[0] = *(const float4*)&Bs[kk][tx * 4];
            *(float4*)&b[4] = *(const float4*)&Bs[kk][64 + tx * 4];
#pragma unroll
            for (int i = 0; i < 8; i++)
#pragma unroll
                for (int j = 0; j < 8; j++)
                    acc[i][j] += a[i] * b[j];
        }
        __syncthreads();
    }

#pragma unroll
    for (int i = 0; i < 8; i++) {
        int m = row0 + ((i < 4) ? (ty * 4 + i) : (64 + ty * 4 + i - 4));
        float bb = bias[m];
        int n1 = col0 + tx * 4;
        int n2 = col0 + 64 + tx * 4;
        if (n1 < Nn) {
            float4 v;
            v.x = acc[i][0] + bb; v.y = acc[i][1] + bb;
            v.z = acc[i][2] + bb; v.w = acc[i][3] + bb;
            *(float4*)&C[(long)m * Nn + n1] = v;
        }
        if (n2 < Nn) {
            float4 v;
            v.x = acc[i][4] + bb; v.y = acc[i][5] + bb;
            v.z = acc[i][6] + bb; v.w = acc[i][7] + bb;
            *(float4*)&C[(long)m * Nn + n2] = v;
        }
    }
}

struct ProjW {
    const float *Wk, *Wq, *Wv;
    const float *bk, *bq, *bv;
};

__global__ __launch_bounds__(256) void proj_kernel(ProjW pw, const float* __restrict__ xs,
                                                   float* __restrict__ qkv) {
    int z = blockIdx.z;  // 0=K, 1=Q, 2=V
    const float* A = (z == 0) ? pw.Wk : ((z == 1) ? pw.Wq : pw.Wv);
    const float* b = (z == 0) ? pw.bk : ((z == 1) ? pw.bq : pw.bv);
    gemm_tile(A, xs, b, qkv + (long)z * BATCH_QKV, HD, PN, DD);
}

__global__ __launch_bounds__(256) void outproj_kernel(const float* __restrict__ Wo,
                                                      const float* __restrict__ att,
                                                      const float* __restrict__ bo,
                                                      float* __restrict__ out) {
    long z = blockIdx.z;  // batch
    gemm_tile(Wo, att + z * BATCH_QKV, bo, out + z * (long)BATCH_X, DD, PN, HD);
}

// ---------------- attention kernel ------------------
// grid: (WIN=64, HEADS=8); 256 threads
// smem carve:
//   buf   : 256*68 floats   (K/Q chunks, then V, then staged output)
//   Ssm   : 49*52 floats
//   rel_s : 169 floats
//   fm_s  : 49 ints, col_s : 49 ints
#define ATTN_SMEM_FLOATS (17408 + 2548 + 169 + 98)
#define ATTN_SMEM_BYTES  (ATTN_SMEM_FLOATS * 4)

__global__ __launch_bounds__(256) void attn_kernel(const float* __restrict__ qkv,
                                                   const float* __restrict__ rel_code,
                                                   float* __restrict__ outbuf) {
    extern __shared__ float sm[];
    float* buf   = sm;                       // 17408
    float* Ssm   = sm + 17408;               // 2548
    float* rel_s = sm + 17408 + 2548;        // 169
    int*   fm_s  = (int*)(sm + 17408 + 2548 + 169);
    int*   col_s = fm_s + 49;

    int g = blockIdx.x;
    int h = blockIdx.y;
    int gy = g >> 3, gx = g & 7;
    int tid = threadIdx.x;

    if (tid < 169) rel_s[tid] = rel_code[tid * HEADS + h];
    if (tid < P) {
        int ty = tid / WS, tx = tid % WS;
        int rr = gy * WS + ty, cc = gx * WS + tx;
        int ry = (rr < 49) ? 0 : ((rr < 53) ? 1 : 2);
        int rx = (cc < 49) ? 0 : ((cc < 53) ? 1 : 2);
        fm_s[tid]  = ry * 3 + rx;
        col_s[tid] = rr * CH + cc;
    }
    __syncthreads();

    int txc = tid & 15, tyc = tid >> 4;   // p-tile via txc, q-tile via tyc
    float acc[4][4];
#pragma unroll
    for (int i = 0; i < 4; i++)
#pragma unroll
        for (int j = 0; j < 4; j++) acc[i][j] = 0.f;

    // ---- S = K^T Q over d in two 128-chunks ----
    for (int c = 0; c < 2; c++) {
        for (int i = tid; i < 128 * 64; i += 256) {
            int d = i >> 6;
            int p = i & 63;
            float kv = 0.f, qv = 0.f;
            if (p < P) {
                int dd = c * 128 + d;
                long off = (long)(h * DD + dd) * PN + col_s[p];
                kv = qkv[off];                      // K
                qv = qkv[(long)BATCH_QKV + off];    // Q
            }
            buf[d * 68 + p]        = kv;
            buf[8704 + d * 68 + p] = qv;
        }
        __syncthreads();
#pragma unroll 4
        for (int d = 0; d < 128; d++) {
            float4 kf = *(const float4*)&buf[d * 68 + txc * 4];
            float4 qf = *(const float4*)&buf[8704 + d * 68 + tyc * 4];
            float kk[4] = {kf.x, kf.y, kf.z, kf.w};
            float qq[4] = {qf.x, qf.y, qf.z, qf.w};
#pragma unroll
            for (int i = 0; i < 4; i++)
#pragma unroll
                for (int j = 0; j < 4; j++)
                    acc[i][j] += kk[i] * qq[j];
        }
        __syncthreads();
    }

    // ---- scale + mask + relative bias -> Ssm[p][q] ----
    const float scale = 0.0625f;  // 1/sqrt(256)
#pragma unroll
    for (int i = 0; i < 4; i++) {
        int p = txc * 4 + i;
        if (p >= P) continue;
        int py = p / WS, px = p % WS;
        int fmp = fm_s[p];
#pragma unroll
        for (int j = 0; j < 4; j++) {
            int q = tyc * 4 + j;
            if (q >= P) continue;
            int qy = q / WS, qx = q % WS;
            float r = rel_s[(py - qy + 6) + 13 * (px - qx + 6)];
            float mval = (fmp == fm_s[q]) ? 0.f : -100.f;
            Ssm[p * 52 + q] = acc[i][j] * scale + mval + r;
        }
    }
    __syncthreads();

    // ---- softmax over p (per column q) ----
    if (tid < P) {
        float m = -1e30f;
        for (int p = 0; p < P; p++) m = fmaxf(m, Ssm[p * 52 + tid]);
        float s = 0.f;
        for (int p = 0; p < P; p++) {
            float e = __expf(Ssm[p * 52 + tid] - m);
            Ssm[p * 52 + tid] = e;
            s += e;
        }
        float inv = 1.f / s;
        for (int p = 0; p < P; p++) Ssm[p * 52 + tid] *= inv;
    }
    __syncthreads();

    // ---- load V (full 256 rows) into buf ----
    for (int i = tid; i < 256 * 64; i += 256) {
        int d = i >> 6;
        int p = i & 63;
        float vv = 0.f;
        if (p < P)
            vv = qkv[2L * BATCH_QKV + (long)(h * DD + d) * PN + col_s[p]];
        buf[d * 68 + p] = vv;
    }
    __syncthreads();

    // ---- AV: thread = d row; V cached in registers ----
    int d = tid;
    float v[P];
#pragma unroll
    for (int p = 0; p < P; p++) v[p] = buf[d * 68 + p];
    __syncthreads();   // buf now free for output staging

    // out[d][q] -> staged in buf[d*52+q]
    for (int q0 = 0; q0 < 48; q0 += 4) {
        float a0 = 0.f, a1 = 0.f, a2 = 0.f, a3 = 0.f;
#pragma unroll
        for (int p = 0; p < P; p++) {
            float4 w = *(const float4*)&Ssm[p * 52 + q0];
            a0 += v[p] * w.x;
            a1 += v[p] * w.y;
            a2 += v[p] * w.z;
            a3 += v[p] * w.w;
        }
        float4 o; o.x = a0; o.y = a1; o.z = a2; o.w = a3;
        *(float4*)&buf[d * 52 + q0] = o;
    }
    {
        float a = 0.f;
#pragma unroll
        for (int p = 0; p < P; p++) a += v[p] * Ssm[p * 52 + 48];
        buf[d * 52 + 48] = a;
    }
    __syncthreads();

    // ---- coalesced write-out ----
    for (int i = tid; i < 256 * P; i += 256) {
        int dr = i / P;
        int q  = i % P;
        outbuf[(long)(h * DD + dr) * PN + col_s[q]] = buf[dr * 52 + q];
    }
}

// ---------------- launch -----------------------------
extern "C" void kernel_launch(void* const* d_in, const int* in_sizes, int n_in,
                              void* d_out, int out_size) {
    const float* inputs = (const float*)d_in[0];
    const float* Wk = (const float*)d_in[1];
    const float* bk = (const float*)d_in[2];
    const float* Wq = (const float*)d_in[3];
    const float* bq = (const float*)d_in[4];
    const float* Wv = (const float*)d_in[5];
    const float* bv = (const float*)d_in[6];
    const float* Wo = (const float*)d_in[7];
    const float* bo = (const float*)d_in[8];
    const float* rel = (const float*)d_in[9];
    float* out = (float*)d_out;

    float *xs, *qkv, *att;
    cudaGetSymbolAddress((void**)&xs, g_xs);
    cudaGetSymbolAddress((void**)&qkv, g_qkv);
    cudaGetSymbolAddress((void**)&att, g_att);

    cudaFuncSetAttribute(attn_kernel, cudaFuncAttributeMaxDynamicSharedMemorySize,
                         ATTN_SMEM_BYTES);

    // 1) pixel-space shift
    {
        long total = (long)NB * DD * PN;
        int blocks = (int)((total + 255) / 256);
        shift_kernel<<<blocks, 256>>>(inputs, xs);
    }

    // 2-3) per-batch: projections then attention (stream order = dependency)
    ProjW pw{Wk, Wq, Wv, bk, bq, bv};
    for (int n = 0; n < NB; n++) {
        proj_kernel<<<dim3(25, 16, 3), 256>>>(pw, xs + (long)n * BATCH_X, qkv);
        attn_kernel<<<dim3(WIN, HEADS), 256, ATTN_SMEM_BYTES>>>(
            qkv, rel, att + (long)n * BATCH_QKV);
    }

    // 4) output projection, all batches
    outproj_kernel<<<dim3(25, 2, 8), 256>>>(Wo, att, bo, out);
}

// round 2
// speedup vs baseline: 1.2604x; 1.2604x over previous
#include <cuda_runtime.h>
#include <math.h>

// ---------------- problem constants ----------------
#define NB    8
#define DD    256
#define HEADS 8
#define PN    3136
#define CH    56
#define WS    7
#define P     49
#define WIN   64
#define HD    2048
#define PIX   224

#define BATCH_X   ((long)DD*PN)     // 802816
#define BATCH_QKV ((long)HD*PN)     // 6422528

// ---------------- static scratch -------------------
__device__ float g_xs[(long)NB * DD * PN];            // shifted input (window-ordered cols)
__device__ float g_qkv[(long)NB * 3 * HD * PN];       // all-batch K,Q,V  616MB
__device__ float g_att[(long)NB * HD * PN];           // attention out (window-ordered cols)

// window-ordered column c -> spatial patch index
__device__ __forceinline__ int spatial_col(int c) {
    int win = c / 49, pos = c - win * 49;
    int wy = win >> 3, wx = win & 7;
    int py = pos / 7,  px = pos - py * 7;
    return (wy * 7 + py) * CH + (wx * 7 + px);
}

// ---------------- shift kernel ---------------------
// output layout: [NB][DD][PN] with PN index window-ordered
__global__ void shift_kernel(const float* __restrict__ in, float* __restrict__ out) {
    long idx = (long)blockIdx.x * blockDim.x + threadIdx.x;
    if (idx >= (long)NB * DD * PN) return;
    int c  = (int)(idx % PN);
    int d  = (int)((idx / PN) % DD);
    int nb = (int)(idx / ((long)DD * PN));
    // window-ordered column -> spatial patch (i,j)
    int win = c / 49, pos = c - win * 49;
    int wy = win >> 3, wx = win & 7;
    int py = pos / 7,  px = pos - py * 7;
    int i = wy * 7 + py, j = wx * 7 + px;
    // pixel-space roll by 3
    int ch = d >> 4;
    int dpy = (d >> 2) & 3;
    int dpx = d & 3;
    int r = i * 4 + dpy, s = j * 4 + dpx;
    int rs = (r + PIX - 3) % PIX;
    int ss = (s + PIX - 3) % PIX;
    int ip = rs >> 2, jp = ss >> 2;
    int dp = (ch << 4) + ((rs & 3) << 2) + (ss & 3);
    int pp = ip * CH + jp;  // spatial (input is spatial layout)
    out[idx] = in[((long)nb * DD + dp) * PN + pp];
}

// ------------- double-buffered sgemm tile ------------
// BM x 128 x 8 tile, 256 threads. PERM: scatter-store through spatial_col.
template<int BM, bool PERM>
__device__ __forceinline__ void gemm_tile_t(
    const float* __restrict__ A,   // [M,K] row-major
    const float* __restrict__ B,   // [K,Nn] row-major
    const float* __restrict__ bias,// [M]
    float* __restrict__ C,         // [M,Nn]
    int Nn, int K)
{
    constexpr int RI = BM / 16;
    __shared__ float As[2][8][BM];
    __shared__ float Bs[2][8][128];

    const int tid  = threadIdx.x;
    const int row0 = blockIdx.y * BM;
    const int col0 = blockIdx.x * 128;
    const int bRow = tid >> 5;
    const int bCol = (tid & 31) << 2;
    const int tx = tid & 15;
    const int ty = tid >> 4;

    const float* Bptr = B + (long)bRow * Nn + col0 + bCol;
    const bool bvalid = (col0 + bCol) < Nn;

    int aRow, aCol;
    if (BM == 128) { aRow = tid >> 1; aCol = (tid & 1) << 2; }
    else           { aRow = tid >> 2; aCol = (tid & 3) << 1; }
    const float* Aptr = A + (long)(row0 + aRow) * K + aCol;

    float acc[RI][8];
#pragma unroll
    for (int i = 0; i < RI; i++)
#pragma unroll
        for (int j = 0; j < 8; j++) acc[i][j] = 0.f;

    float4 bv = bvalid ? *(const float4*)Bptr : make_float4(0.f, 0.f, 0.f, 0.f);
    float4 av4 = make_float4(0.f, 0.f, 0.f, 0.f);
    float2 av2 = make_float2(0.f, 0.f);
    if (BM == 128) av4 = *(const float4*)Aptr;
    else           av2 = *(const float2*)Aptr;

    for (int k0 = 0; k0 < K; k0 += 8) {
        const int bf = (k0 >> 3) & 1;
        if (BM == 128) {
            As[bf][aCol + 0][aRow] = av4.x;
            As[bf][aCol + 1][aRow] = av4.y;
            As[bf][aCol + 2][aRow] = av4.z;
            As[bf][aCol + 3][aRow] = av4.w;
        } else {
            As[bf][aCol + 0][aRow] = av2.x;
            As[bf][aCol + 1][aRow] = av2.y;
        }
        *(float4*)&Bs[bf][bRow][bCol] = bv;
        __syncthreads();
        if (k0 + 8 < K) {
            bv = bvalid ? *(const float4*)(Bptr + (long)(k0 + 8) * Nn)
                        : make_float4(0.f, 0.f, 0.f, 0.f);
            if (BM == 128) av4 = *(const float4*)(Aptr + k0 + 8);
            else           av2 = *(const float2*)(Aptr + k0 + 8);
        }
#pragma unroll
        for (int kk = 0; kk < 8; kk++) {
            float a[RI], b[8];
            *(float4*)&b[0] = *(const float4*)&Bs[bf][kk][tx * 4];
            *(float4*)&b[4] = *(const float4*)&Bs[bf][kk][64 + tx * 4];
            *(float4*)&a[0] = *(const float4*)&As[bf][kk][ty * 4];
            if (BM == 128)
                *(float4*)&a[4] = *(const float4*)&As[bf][kk][64 + ty * 4];
#pragma unroll
            for (int i = 0; i < RI; i++)
#pragma unroll
                for (int j = 0; j < 8; j++)
                    acc[i][j] = fmaf(a[i], b[j], acc[i][j]);
        }
    }

#pragma unroll
    for (int i = 0; i < RI; i++) {
        int m;
        if (BM == 128) m = row0 + ((i < 4) ? (ty * 4 + i) : (64 + ty * 4 + i - 4));
        else           m = row0 + ty * 4 + i;
        const float bb = bias[m];
        const int n1 = col0 + tx * 4;
        const int n2 = col0 + 64 + tx * 4;
        if (!PERM) {
            if (n1 < Nn) {
                float4 v = {acc[i][0] + bb, acc[i][1] + bb, acc[i][2] + bb, acc[i][3] + bb};
                *(float4*)&C[(long)m * Nn + n1] = v;
            }
            if (n2 < Nn) {
                float4 v = {acc[i][4] + bb, acc[i][5] + bb, acc[i][6] + bb, acc[i][7] + bb};
                *(float4*)&C[(long)m * Nn + n2] = v;
            }
        } else {
#pragma unroll
            for (int j = 0; j < 4; j++) {
                int c1 = n1 + j;
                if (c1 < Nn) C[(long)m * Nn + spatial_col(c1)] = acc[i][j] + bb;
                int c2 = n2 + j;
                if (c2 < Nn) C[(long)m * Nn + spatial_col(c2)] = acc[i][4 + j] + bb;
            }
        }
    }
}

__global__ __launch_bounds__(256) void proj_kernel(
    const float* __restrict__ Wk, const float* __restrict__ Wq, const float* __restrict__ Wv,
    const float* __restrict__ bk, const float* __restrict__ bq, const float* __restrict__ bv,
    const float* __restrict__ xs, float* __restrict__ qkv)
{
    int z = blockIdx.z;
    int n = z / 3, m = z - n * 3;
    const float* A = (m == 0) ? Wk : ((m == 1) ? Wq : Wv);
    const float* b = (m == 0) ? bk : ((m == 1) ? bq : bv);
    gemm_tile_t<128, false>(A, xs + (long)n * BATCH_X, b,
                            qkv + ((long)n * 3 + m) * BATCH_QKV, PN, DD);
}

__global__ __launch_bounds__(256) void outproj_kernel(
    const float* __restrict__ Wo, const float* __restrict__ bo,
    const float* __restrict__ att, float* __restrict__ out)
{
    int n = blockIdx.z;
    gemm_tile_t<64, true>(Wo, att + (long)n * BATCH_QKV, bo,
                          out + (long)n * BATCH_X, PN, HD);
}

// ---------------- attention kernel ------------------
// grid (WIN, HEADS, NB), 256 threads. All loads fully coalesced (window layout).
#define ATTN_SMEM_FLOATS (17408 + 2548 + 169 + 49)
#define ATTN_SMEM_BYTES  (ATTN_SMEM_FLOATS * 4)

__global__ __launch_bounds__(256) void attn_kernel(const float* __restrict__ qkv,
                                                   const float* __restrict__ rel_code,
                                                   float* __restrict__ att) {
    extern __shared__ float sm[];
    float* buf   = sm;                       // 17408 : K(128x68)+Q(128x68), then V, then out
    float* Ssm   = sm + 17408;               // 2548  : 49 x 52
    float* rel_s = sm + 17408 + 2548;        // 169
    int*   fm_s  = (int*)(rel_s + 169);      // 49

    const int g  = blockIdx.x;
    const int h  = blockIdx.y;
    const int nb = blockIdx.z;
    const int tid = threadIdx.x;

    const long baseK = ((long)nb * 3 + 0) * BATCH_QKV + (long)(h * DD) * PN + g * 49;
    const long baseQ = baseK + BATCH_QKV;
    const long baseV = baseK + 2 * BATCH_QKV;

    if (tid < 169) rel_s[tid] = rel_code[tid * HEADS + h];
    if (tid < P) {
        int gy = g >> 3, gx = g & 7;
        int ty = tid / 7, tx = tid - ty * 7;
        int rr = gy * 7 + ty, cc = gx * 7 + tx;
        int ry = (rr < 49) ? 0 : ((rr < 53) ? 1 : 2);
        int rx = (cc < 49) ? 0 : ((cc < 53) ? 1 : 2);
        fm_s[tid] = ry * 3 + rx;
    }
    __syncthreads();

    const int txc = tid & 15, tyc = tid >> 4;
    float acc[4][4];
#pragma unroll
    for (int i = 0; i < 4; i++)
#pragma unroll
        for (int j = 0; j < 4; j++) acc[i][j] = 0.f;

    // ---- S = K^T Q over d in two 128-chunks ----
    for (int c = 0; c < 2; c++) {
        for (int i = tid; i < 128 * 64; i += 256) {
            int d = i >> 6;
            int p = i & 63;
            float kv = 0.f, qv = 0.f;
            if (p < P) {
                long off = (long)(c * 128 + d) * PN + p;
                kv = qkv[baseK + off];
                qv = qkv[baseQ + off];
            }
            buf[d * 68 + p]        = kv;
            buf[8704 + d * 68 + p] = qv;
        }
        __syncthreads();
#pragma unroll 4
        for (int d = 0; d < 128; d++) {
            float4 kf = *(const float4*)&buf[d * 68 + txc * 4];
            float4 qf = *(const float4*)&buf[8704 + d * 68 + tyc * 4];
            float kk[4] = {kf.x, kf.y, kf.z, kf.w};
            float qq[4] = {qf.x, qf.y, qf.z, qf.w};
#pragma unroll
            for (int i = 0; i < 4; i++)
#pragma unroll
                for (int j = 0; j < 4; j++)
                    acc[i][j] += kk[i] * qq[j];
        }
        __syncthreads();
    }

    // ---- scale + mask + relative bias -> Ssm[p][q] ----
    const float scale = 0.0625f;
#pragma unroll
    for (int i = 0; i < 4; i++) {
        int p = txc * 4 + i;
        if (p >= P) continue;
        int py = p / WS, px = p % WS;
        int fmp = fm_s[p];
#pragma unroll
        for (int j = 0; j < 4; j++) {
            int q = tyc * 4 + j;
            if (q >= P) continue;
            int qy = q / WS, qx = q % WS;
            float r = rel_s[(py - qy + 6) + 13 * (px - qx + 6)];
            float mval = (fmp == fm_s[q]) ? 0.f : -100.f;
            Ssm[p * 52 + q] = acc[i][j] * scale + mval + r;
        }
    }
    __syncthreads();

    // ---- softmax over p (per column q) ----
    if (tid < P) {
        float m = -1e30f;
        for (int p = 0; p < P; p++) m = fmaxf(m, Ssm[p * 52 + tid]);
        float s = 0.f;
        for (int p = 0; p < P; p++) {
            float e = __expf(Ssm[p * 52 + tid] - m);
            Ssm[p * 52 + tid] = e;
            s += e;
        }
        float inv = 1.f / s;
        for (int p = 0; p < P; p++) Ssm[p * 52 + tid] *= inv;
    }
    __syncthreads();

    // ---- load V (256 rows) ----
    for (int i = tid; i < 256 * 64; i += 256) {
        int d = i >> 6;
        int p = i & 63;
        float vv = 0.f;
        if (p < P) vv = qkv[baseV + (long)d * PN + p];
        buf[d * 68 + p] = vv;
    }
    __syncthreads();

    // ---- AV: thread = d row; V cached in registers ----
    const int d = tid;
    float v[P];
#pragma unroll
    for (int p = 0; p < P; p++) v[p] = buf[d * 68 + p];
    __syncthreads();

    for (int q0 = 0; q0 < 48; q0 += 4) {
        float a0 = 0.f, a1 = 0.f, a2 = 0.f, a3 = 0.f;
#pragma unroll
        for (int p = 0; p < P; p++) {
            float4 w = *(const float4*)&Ssm[p * 52 + q0];
            a0 += v[p] * w.x;
            a1 += v[p] * w.y;
            a2 += v[p] * w.z;
            a3 += v[p] * w.w;
        }
        float4 o; o.x = a0; o.y = a1; o.z = a2; o.w = a3;
        *(float4*)&buf[d * 52 + q0] = o;
    }
    {
        float a = 0.f;
#pragma unroll
        for (int p = 0; p < P; p++) a += v[p] * Ssm[p * 52 + 48];
        buf[d * 52 + 48] = a;
    }
    __syncthreads();

    // ---- coalesced write-out (window layout) ----
    const long outbase = (long)nb * BATCH_QKV + (long)(h * DD) * PN + g * 49;
    for (int i = tid; i < 256 * P; i += 256) {
        int dr = i / P;
        int q  = i - dr * P;
        att[outbase + (long)dr * PN + q] = buf[dr * 52 + q];
    }
}

// ---------------- launch -----------------------------
extern "C" void kernel_launch(void* const* d_in, const int* in_sizes, int n_in,
                              void* d_out, int out_size) {
    const float* inputs = (const float*)d_in[0];
    const float* Wk = (const float*)d_in[1];
    const float* bk = (const float*)d_in[2];
    const float* Wq = (const float*)d_in[3];
    const float* bq = (const float*)d_in[4];
    const float* Wv = (const float*)d_in[5];
    const float* bv = (const float*)d_in[6];
    const float* Wo = (const float*)d_in[7];
    const float* bo = (const float*)d_in[8];
    const float* rel = (const float*)d_in[9];
    float* out = (float*)d_out;

    float *xs, *qkv, *att;
    cudaGetSymbolAddress((void**)&xs, g_xs);
    cudaGetSymbolAddress((void**)&qkv, g_qkv);
    cudaGetSymbolAddress((void**)&att, g_att);

    cudaFuncSetAttribute(attn_kernel, cudaFuncAttributeMaxDynamicSharedMemorySize,
                         ATTN_SMEM_BYTES);

    {
        long total = (long)NB * DD * PN;
        int blocks = (int)((total + 255) / 256);
        shift_kernel<<<blocks, 256>>>(inputs, xs);
    }

    proj_kernel<<<dim3(25, 16, 24), 256>>>(Wk, Wq, Wv, bk, bq, bv, xs, qkv);
    attn_kernel<<<dim3(WIN, HEADS, NB), 256, ATTN_SMEM_BYTES>>>(qkv, rel, att);
    outproj_kernel<<<dim3(25, 4, 8), 256>>>(Wo, bo, att, out);
}

// round 4
// speedup vs baseline: 1.8793x; 1.4910x over previous
#include <cuda_runtime.h>
#include <cuda_bf16.h>
#include <cstdint>
#include <math.h>

// ---------------- problem constants ----------------
#define NB    8
#define DD    256
#define HEADS 8
#define PN    3136
#define CH    56
#define WS    7
#define P     49
#define WIN   64
#define HD    2048
#define PIX   224
#define NPAD  3200

#define BATCH_X   ((long)DD*PN)
#define BATCH_QKV ((long)HD*PN)

// ---------------- static scratch -------------------
__device__ float g_xs[(long)NB * DD * PN];
__device__ float g_qkv[(long)NB * 3 * HD * PN];
__device__ float g_att[(long)NB * HD * PN];
__device__ __align__(16) __nv_bfloat16 g_Wc_hi[6144 * 256];
__device__ __align__(16) __nv_bfloat16 g_Wc_lo[6144 * 256];
__device__ __align__(16) __nv_bfloat16 g_Wo_hi[256 * 2048];
__device__ __align__(16) __nv_bfloat16 g_Wo_lo[256 * 2048];
__device__ float g_bias_c[6144];
__device__ __align__(16) __nv_bfloat16 g_xt_hi[(long)NB * NPAD * DD];
__device__ __align__(16) __nv_bfloat16 g_xt_lo[(long)NB * NPAD * DD];
__device__ __align__(16) __nv_bfloat16 g_at_hi[(long)NB * NPAD * HD];
__device__ __align__(16) __nv_bfloat16 g_at_lo[(long)NB * NPAD * HD];

// ---------------- PTX helpers ----------------------
__device__ __forceinline__ uint32_t smem_u32(const void* p) {
    uint32_t a;
    asm("{ .reg .u64 t; cvta.to.shared.u64 t, %1; cvt.u32.u64 %0, t; }"
        : "=r"(a) : "l"(p));
    return a;
}

#define CP16(dst, src) \
    asm volatile("cp.async.cg.shared.global [%0], [%1], 16;" :: "r"(dst), "l"(src))
#define CP_COMMIT() asm volatile("cp.async.commit_group;" ::: "memory")
#define CP_WAIT(n)  asm volatile("cp.async.wait_group %0;" :: "n"(n) : "memory")

#define LDSM4(r, addr) \
    asm volatile("ldmatrix.sync.aligned.m8n8.x4.shared.b16 {%0,%1,%2,%3}, [%4];" \
        : "=r"((r)[0]), "=r"((r)[1]), "=r"((r)[2]), "=r"((r)[3]) : "r"(addr))

#define MMA_BF16(c, a, b0, b1) \
    asm volatile("mma.sync.aligned.m16n8k16.row.col.f32.bf16.bf16.f32 " \
        "{%0,%1,%2,%3}, {%4,%5,%6,%7}, {%8,%9}, {%0,%1,%2,%3};" \
        : "+f"((c)[0]), "+f"((c)[1]), "+f"((c)[2]), "+f"((c)[3]) \
        : "r"((a)[0]), "r"((a)[1]), "r"((a)[2]), "r"((a)[3]), "r"(b0), "r"(b1))

// window-ordered column -> spatial patch index
__device__ __forceinline__ int spatial_col(int c) {
    int win = c / 49, pos = c - win * 49;
    int wy = win >> 3, wx = win & 7;
    int py = pos / 7,  px = pos - py * 7;
    return (wy * 7 + py) * CH + (wx * 7 + px);
}

// ---------------- shift kernel ---------------------
__global__ void shift_kernel(const float* __restrict__ in, float* __restrict__ out) {
    long idx = (long)blockIdx.x * blockDim.x + threadIdx.x;
    if (idx >= (long)NB * DD * PN) return;
    int c  = (int)(idx % PN);
    int d  = (int)((idx / PN) % DD);
    int nb = (int)(idx / ((long)DD * PN));
    int win = c / 49, pos = c - win * 49;
    int wy = win >> 3, wx = win & 7;
    int py = pos / 7,  px = pos - py * 7;
    int i = wy * 7 + py, j = wx * 7 + px;
    int ch = d >> 4;
    int r = i * 4 + ((d >> 2) & 3), s = j * 4 + (d & 3);
    int rs = (r + PIX - 3) % PIX;
    int ss = (s + PIX - 3) % PIX;
    int dp = (ch << 4) + ((rs & 3) << 2) + (ss & 3);
    int pp = (rs >> 2) * CH + (ss >> 2);
    out[idx] = in[((long)nb * DD + dp) * PN + pp];
}

// ------------- weight conversion -------------------
__global__ void convert_weights(const float* __restrict__ Wk, const float* __restrict__ Wq,
                                const float* __restrict__ Wv, const float* __restrict__ bk,
                                const float* __restrict__ bq, const float* __restrict__ bv,
                                const float* __restrict__ Wo) {
    const long NW = 6144L * 256, NO = 256L * 2048;
    long i = (long)blockIdx.x * blockDim.x + threadIdx.x;
    if (i < NW) {
        int row = (int)(i >> 8), col = (int)(i & 255);
        const float* src = (row < 2048) ? Wk : ((row < 4096) ? Wq : Wv);
        float x = src[(long)(row & 2047) * 256 + col];
        __nv_bfloat16 h = __float2bfloat16(x);
        g_Wc_hi[i] = h;
        g_Wc_lo[i] = __float2bfloat16(x - __bfloat162float(h));
    } else if (i < NW + NO) {
        long j = i - NW;
        float x = Wo[j];
        __nv_bfloat16 h = __float2bfloat16(x);
        g_Wo_hi[j] = h;
        g_Wo_lo[j] = __float2bfloat16(x - __bfloat162float(h));
    } else if (i < NW + NO + 6144) {
        int r = (int)(i - NW - NO);
        const float* sb = (r < 2048) ? bk : ((r < 4096) ? bq : bv);
        g_bias_c[r] = sb[r & 2047];
    }
}

// ------------- transpose + hi/lo convert -----------
__global__ void transpose_conv(const float* __restrict__ in, __nv_bfloat16* __restrict__ hi,
                               __nv_bfloat16* __restrict__ lo, int R,
                               long inStride, long outStride) {
    __shared__ float t[32][33];
    int z = blockIdx.z;
    const float* I = in + (long)z * inStride;
    int c0 = blockIdx.x * 32, r0 = blockIdx.y * 32;
    int tx = threadIdx.x, ty = threadIdx.y;
#pragma unroll
    for (int i = 0; i < 32; i += 8) {
        int col = c0 + tx, row = r0 + ty + i;
        t[ty + i][tx] = (col < PN) ? I[(long)row * PN + col] : 0.f;
    }
    __syncthreads();
    __nv_bfloat16* H = hi + (long)z * outStride;
    __nv_bfloat16* L = lo + (long)z * outStride;
#pragma unroll
    for (int i = 0; i < 32; i += 8) {
        int orow = c0 + ty + i, ocol = r0 + tx;
        float v = t[tx][ty + i];
        __nv_bfloat16 h = __float2bfloat16(v);
        H[(long)orow * R + ocol] = h;
        L[(long)orow * R + ocol] = __float2bfloat16(v - __bfloat162float(h));
    }
}

// ------------- HMMA bf16x3 GEMM --------------------
// C[128m x 128n] = sum_k A[m,k]*B[n,k]; A,B in (hi,lo) bf16 pairs.
// mode 0: proj   C = qkv + z*3*BQKV, row rg -> (rg>>11)*BQKV + (rg&2047)*PN
// mode 1: outproj C = out + z*BX, column spatial permutation
#define TSTRIDE 40                       // halves per smem row (32 + 8 pad)
#define TILE_HALVES (128 * TSTRIDE)      // 5120
#define STAGE_HALVES (4 * TILE_HALVES)   // 20480
#define GEMM_SMEM (2 * STAGE_HALVES * 2) // 81920 bytes

__global__ __launch_bounds__(256, 1) void gemm_kernel(
    const __nv_bfloat16* __restrict__ Ahi, const __nv_bfloat16* __restrict__ Alo,
    const __nv_bfloat16* __restrict__ Bhi, const __nv_bfloat16* __restrict__ Blo,
    const float* __restrict__ bias, float* __restrict__ Cbase,
    int K, long bStride, int mode)
{
    extern __shared__ __nv_bfloat16 sh[];
    const int tid = threadIdx.x;
    const int lane = tid & 31;
    const int wid = tid >> 5;
    const int wm = wid & 3;          // 4 m-warps
    const int wn = wid >> 2;         // 2 n-warps
    const int z  = blockIdx.z;
    const int m0g = blockIdx.y * 128;
    const int n0g = blockIdx.x * 128;
    const int T = K >> 5;

    const __nv_bfloat16* srcs[4];
    srcs[0] = Ahi + (long)m0g * K;
    srcs[1] = Alo + (long)m0g * K;
    srcs[2] = Bhi + (long)z * bStride + (long)n0g * K;
    srcs[3] = Blo + (long)z * bStride + (long)n0g * K;
    float* C = Cbase + ((mode == 0) ? (long)z * 3 * BATCH_QKV : (long)z * BATCH_X);

    const uint32_t smu = smem_u32(sh);

    // per-thread load coords: cid = tid + j*256 -> row = cid/4, c8 = (cid%4)*8
    const int ldr0 = tid >> 2;
    const int ldc0 = (tid & 3) << 3;

    float acc[2][8][4];
#pragma unroll
    for (int a = 0; a < 2; a++)
#pragma unroll
        for (int b = 0; b < 8; b++)
#pragma unroll
            for (int cc = 0; cc < 4; cc++) acc[a][b][cc] = 0.f;

    // ldmatrix per-thread address components
    // A: row = wm*32 + mt*16 + ((lane>>3)&1)*8 + (lane&7), col = k16*16 + (lane>>4)*8
    const int a_r = wm * 32 + ((lane >> 3) & 1) * 8 + (lane & 7);
    const int a_c = (lane >> 4) * 8;
    // B: row = wn*64 + nt2*16 + (lane>>4)*8 + (lane&7), col = k16*16 + ((lane>>3)&1)*8
    const int b_r = wn * 64 + (lane >> 4) * 8 + (lane & 7);
    const int b_c = ((lane >> 3) & 1) * 8;

    // ---- preload stage 0 ----
#pragma unroll
    for (int tile = 0; tile < 4; tile++) {
#pragma unroll
        for (int j = 0; j < 2; j++) {
            int r = ldr0 + j * 64;
            uint32_t dst = smu + (tile * TILE_HALVES + r * TSTRIDE + ldc0) * 2;
            CP16(dst, srcs[tile] + (long)r * K + ldc0);
        }
    }
    CP_COMMIT();

    for (int t = 0; t < T; t++) {
        if (t + 1 < T) {
            const int s2 = (t + 1) & 1;
#pragma unroll
            for (int tile = 0; tile < 4; tile++) {
#pragma unroll
                for (int j = 0; j < 2; j++) {
                    int r = ldr0 + j * 64;
                    uint32_t dst = smu +
                        (s2 * STAGE_HALVES + tile * TILE_HALVES + r * TSTRIDE + ldc0) * 2;
                    CP16(dst, srcs[tile] + (long)r * K + (t + 1) * 32 + ldc0);
                }
            }
            CP_COMMIT();
            CP_WAIT(1);
        } else {
            CP_WAIT(0);
        }
        __syncthreads();

        const uint32_t sb = smu + ((t & 1) * STAGE_HALVES) * 2;
        const uint32_t sAh = sb;
        const uint32_t sAl = sb + TILE_HALVES * 2;
        const uint32_t sBh = sb + 2 * TILE_HALVES * 2;
        const uint32_t sBl = sb + 3 * TILE_HALVES * 2;

#pragma unroll
        for (int k16 = 0; k16 < 2; k16++) {
            uint32_t ah[2][4], al[2][4];
#pragma unroll
            for (int mt = 0; mt < 2; mt++) {
                uint32_t off = ((a_r + mt * 16) * TSTRIDE + a_c + k16 * 16) * 2;
                LDSM4(ah[mt], sAh + off);
                LDSM4(al[mt], sAl + off);
            }
#pragma unroll
            for (int nt2 = 0; nt2 < 4; nt2++) {
                uint32_t bh[4], bl[4];
                uint32_t off = ((b_r + nt2 * 16) * TSTRIDE + b_c + k16 * 16) * 2;
                LDSM4(bh, sBh + off);
                LDSM4(bl, sBl + off);
#pragma unroll
                for (int mt = 0; mt < 2; mt++) {
#pragma unroll
                    for (int sn = 0; sn < 2; sn++) {
                        float* cc = acc[mt][nt2 * 2 + sn];
                        MMA_BF16(cc, ah[mt], bh[sn * 2], bh[sn * 2 + 1]);
                        MMA_BF16(cc, ah[mt], bl[sn * 2], bl[sn * 2 + 1]);
                        MMA_BF16(cc, al[mt], bh[sn * 2], bh[sn * 2 + 1]);
                    }
                }
            }
        }
        __syncthreads();
    }

    // ---- epilogue: direct global stores ----
#pragma unroll
    for (int mt = 0; mt < 2; mt++) {
#pragma unroll
        for (int half = 0; half < 2; half++) {
            int m = m0g + wm * 32 + mt * 16 + (lane >> 2) + half * 8;
            float bb = bias[m];
            long rowoff;
            if (mode == 0)
                rowoff = (long)(m >> 11) * BATCH_QKV + (long)(m & 2047) * PN;
            else
                rowoff = (long)m * PN;
#pragma unroll
            for (int nt = 0; nt < 8; nt++) {
                int n = n0g + wn * 64 + nt * 8 + ((lane & 3) << 1);
                if (n >= PN) continue;
                float v0 = acc[mt][nt][half * 2 + 0] + bb;
                float v1 = acc[mt][nt][half * 2 + 1] + bb;
                if (mode == 0) {
                    float2 st; st.x = v0; st.y = v1;
                    *(float2*)&C[rowoff + n] = st;
                } else {
                    C[rowoff + spatial_col(n)] = v0;
                    C[rowoff + spatial_col(n + 1)] = v1;
                }
            }
        }
    }
}

// ---------------- attention kernel ------------------
#define ATTN_SMEM_FLOATS (17408 + 2548 + 169 + 49)
#define ATTN_SMEM_BYTES  (ATTN_SMEM_FLOATS * 4)

__global__ __launch_bounds__(256) void attn_kernel(const float* __restrict__ qkv,
                                                   const float* __restrict__ rel_code,
                                                   float* __restrict__ att) {
    extern __shared__ float sm[];
    float* buf   = sm;
    float* Ssm   = sm + 17408;
    float* rel_s = sm + 17408 + 2548;
    int*   fm_s  = (int*)(rel_s + 169);

    const int g  = blockIdx.x;
    const int h  = blockIdx.y;
    const int nb = blockIdx.z;
    const int tid = threadIdx.x;

    const long baseK = ((long)nb * 3 + 0) * BATCH_QKV + (long)(h * DD) * PN + g * 49;
    const long baseQ = baseK + BATCH_QKV;
    const long baseV = baseK + 2 * BATCH_QKV;

    if (tid < 169) rel_s[tid] = rel_code[tid * HEADS + h];
    if (tid < P) {
        int gy = g >> 3, gx = g & 7;
        int ty = tid / 7, tx = tid - ty * 7;
        int rr = gy * 7 + ty, cc = gx * 7 + tx;
        int ry = (rr < 49) ? 0 : ((rr < 53) ? 1 : 2);
        int rx = (cc < 49) ? 0 : ((cc < 53) ? 1 : 2);
        fm_s[tid] = ry * 3 + rx;
    }
    __syncthreads();

    const int txc = tid & 15, tyc = tid >> 4;
    float acc[4][4];
#pragma unroll
    for (int i = 0; i < 4; i++)
#pragma unroll
        for (int j = 0; j < 4; j++) acc[i][j] = 0.f;

    for (int c = 0; c < 2; c++) {
        for (int i = tid; i < 128 * 64; i += 256) {
            int d = i >> 6;
            int p = i & 63;
            float kv = 0.f, qv = 0.f;
            if (p < P) {
                long off = (long)(c * 128 + d) * PN + p;
                kv = qkv[baseK + off];
                qv = qkv[baseQ + off];
            }
            buf[d * 68 + p]        = kv;
            buf[8704 + d * 68 + p] = qv;
        }
        __syncthreads();
#pragma unroll 4
        for (int d = 0; d < 128; d++) {
            float4 kf = *(const float4*)&buf[d * 68 + txc * 4];
            float4 qf = *(const float4*)&buf[8704 + d * 68 + tyc * 4];
            float kk[4] = {kf.x, kf.y, kf.z, kf.w};
            float qq[4] = {qf.x, qf.y, qf.z, qf.w};
#pragma unroll
            for (int i = 0; i < 4; i++)
#pragma unroll
                for (int j = 0; j < 4; j++)
                    acc[i][j] += kk[i] * qq[j];
        }
        __syncthreads();
    }

    const float scale = 0.0625f;
#pragma unroll
    for (int i = 0; i < 4; i++) {
        int p = txc * 4 + i;
        if (p >= P) continue;
        int py = p / WS, px = p % WS;
        int fmp = fm_s[p];
#pragma unroll
        for (int j = 0; j < 4; j++) {
            int q = tyc * 4 + j;
            if (q >= P) continue;
            int qy = q / WS, qx = q % WS;
            float r = rel_s[(py - qy + 6) + 13 * (px - qx + 6)];
            float mval = (fmp == fm_s[q]) ? 0.f : -100.f;
            Ssm[p * 52 + q] = acc[i][j] * scale + mval + r;
        }
    }
    __syncthreads();

    if (tid < P) {
        float m = -1e30f;
        for (int p = 0; p < P; p++) m = fmaxf(m, Ssm[p * 52 + tid]);
        float s = 0.f;
        for (int p = 0; p < P; p++) {
            float e = __expf(Ssm[p * 52 + tid] - m);
            Ssm[p * 52 + tid] = e;
            s += e;
        }
        float inv = 1.f / s;
        for (int p = 0; p < P; p++) Ssm[p * 52 + tid] *= inv;
    }
    __syncthreads();

    for (int i = tid; i < 256 * 64; i += 256) {
        int d = i >> 6;
        int p = i & 63;
        float vv = 0.f;
        if (p < P) vv = qkv[baseV + (long)d * PN + p];
        buf[d * 68 + p] = vv;
    }
    __syncthreads();

    const int d = tid;
    float v[P];
#pragma unroll
    for (int p = 0; p < P; p++) v[p] = buf[d * 68 + p];
    __syncthreads();

    for (int q0 = 0; q0 < 48; q0 += 4) {
        float a0 = 0.f, a1 = 0.f, a2 = 0.f, a3 = 0.f;
#pragma unroll
        for (int p = 0; p < P; p++) {
            float4 w = *(const float4*)&Ssm[p * 52 + q0];
            a0 += v[p] * w.x;
            a1 += v[p] * w.y;
            a2 += v[p] * w.z;
            a3 += v[p] * w.w;
        }
        float4 o; o.x = a0; o.y = a1; o.z = a2; o.w = a3;
        *(float4*)&buf[d * 52 + q0] = o;
    }
    {
        float a = 0.f;
#pragma unroll
        for (int p = 0; p < P; p++) a += v[p] * Ssm[p * 52 + 48];
        buf[d * 52 + 48] = a;
    }
    __syncthreads();

    const long outbase = (long)nb * BATCH_QKV + (long)(h * DD) * PN + g * 49;
    for (int i = tid; i < 256 * P; i += 256) {
        int dr = i / P;
        int q  = i - dr * P;
        att[outbase + (long)dr * PN + q] = buf[dr * 52 + q];
    }
}

// ---------------- launch -----------------------------
extern "C" void kernel_launch(void* const* d_in, const int* in_sizes, int n_in,
                              void* d_out, int out_size) {
    const float* inputs = (const float*)d_in[0];
    const float* Wk = (const float*)d_in[1];
    const float* bk = (const float*)d_in[2];
    const float* Wq = (const float*)d_in[3];
    const float* bq = (const float*)d_in[4];
    const float* Wv = (const float*)d_in[5];
    const float* bv = (const float*)d_in[6];
    const float* Wo = (const float*)d_in[7];
    const float* bo = (const float*)d_in[8];
    const float* rel = (const float*)d_in[9];
    float* out = (float*)d_out;

    float *xs, *qkv, *att, *bias_c;
    __nv_bfloat16 *Wc_hi, *Wc_lo, *Wo_hi, *Wo_lo, *xt_hi, *xt_lo, *at_hi, *at_lo;
    cudaGetSymbolAddress((void**)&xs, g_xs);
    cudaGetSymbolAddress((void**)&qkv, g_qkv);
    cudaGetSymbolAddress((void**)&att, g_att);
    cudaGetSymbolAddress((void**)&bias_c, g_bias_c);
    cudaGetSymbolAddress((void**)&Wc_hi, g_Wc_hi);
    cudaGetSymbolAddress((void**)&Wc_lo, g_Wc_lo);
    cudaGetSymbolAddress((void**)&Wo_hi, g_Wo_hi);
    cudaGetSymbolAddress((void**)&Wo_lo, g_Wo_lo);
    cudaGetSymbolAddress((void**)&xt_hi, g_xt_hi);
    cudaGetSymbolAddress((void**)&xt_lo, g_xt_lo);
    cudaGetSymbolAddress((void**)&at_hi, g_at_hi);
    cudaGetSymbolAddress((void**)&at_lo, g_at_lo);

    cudaFuncSetAttribute(attn_kernel, cudaFuncAttributeMaxDynamicSharedMemorySize,
                         ATTN_SMEM_BYTES);
    cudaFuncSetAttribute(gemm_kernel, cudaFuncAttributeMaxDynamicSharedMemorySize,
                         GEMM_SMEM);

    {
        long total = (long)NB * DD * PN;
        shift_kernel<<<(int)((total + 255) / 256), 256>>>(inputs, xs);
    }
    {
        long total = 6144L * 256 + 256L * 2048 + 6144;
        convert_weights<<<(int)((total + 255) / 256), 256>>>(Wk, Wq, Wv, bk, bq, bv, Wo);
    }
    transpose_conv<<<dim3(100, 8, 8), dim3(32, 8)>>>(xs, xt_hi, xt_lo, DD,
                                                     BATCH_X, (long)NPAD * DD);
    gemm_kernel<<<dim3(25, 48, 8), 256, GEMM_SMEM>>>(Wc_hi, Wc_lo, xt_hi, xt_lo,
                                                     bias_c, qkv, 256, (long)NPAD * DD, 0);
    attn_kernel<<<dim3(WIN, HEADS, NB), 256, ATTN_SMEM_BYTES>>>(qkv, rel, att);
    transpose_conv<<<dim3(100, 64, 8), dim3(32, 8)>>>(att, at_hi, at_lo, HD,
                                                      BATCH_QKV, (long)NPAD * HD);
    gemm_kernel<<<dim3(25, 2, 8), 256, GEMM_SMEM>>>(Wo_hi, Wo_lo, at_hi, at_lo,
                                                    bo, out, 2048, (long)NPAD * HD, 1);
}

// round 5
// speedup vs baseline: 2.0277x; 1.0790x over previous
#include <cuda_runtime.h>
#include <cuda_bf16.h>
#include <cstdint>
#include <math.h>

// ---------------- problem constants ----------------
#define NB    8
#define DD    256
#define HEADS 8
#define PN    3136
#define CH    56
#define WS    7
#define P     49
#define WIN   64
#define HD    2048
#define PIX   224
#define NPAD  3200

#define BATCH_X   ((long)DD*PN)
#define BATCH_QKV ((long)HD*PN)

// ---------------- static scratch -------------------
__device__ float g_qkv[(long)NB * 3 * HD * PN];
__device__ __align__(16) __nv_bfloat16 g_Wc_hi[6144 * 256];
__device__ __align__(16) __nv_bfloat16 g_Wc_lo[6144 * 256];
__device__ __align__(16) __nv_bfloat16 g_Wo_hi[256 * 2048];
__device__ __align__(16) __nv_bfloat16 g_Wo_lo[256 * 2048];
__device__ float g_bias_c[6144];
__device__ __align__(16) __nv_bfloat16 g_xt_hi[(long)NB * NPAD * DD];
__device__ __align__(16) __nv_bfloat16 g_xt_lo[(long)NB * NPAD * DD];
__device__ __align__(16) __nv_bfloat16 g_at_hi[(long)NB * NPAD * HD];
__device__ __align__(16) __nv_bfloat16 g_at_lo[(long)NB * NPAD * HD];

// ---------------- PTX helpers ----------------------
__device__ __forceinline__ uint32_t smem_u32(const void* p) {
    uint32_t a;
    asm("{ .reg .u64 t; cvta.to.shared.u64 t, %1; cvt.u32.u64 %0, t; }"
        : "=r"(a) : "l"(p));
    return a;
}

#define CP16(dst, src) \
    asm volatile("cp.async.cg.shared.global [%0], [%1], 16;" :: "r"(dst), "l"(src))
#define CP_COMMIT() asm volatile("cp.async.commit_group;" ::: "memory")
#define CP_WAIT(n)  asm volatile("cp.async.wait_group %0;" :: "n"(n) : "memory")

#define LDSM4(r, addr) \
    asm volatile("ldmatrix.sync.aligned.m8n8.x4.shared.b16 {%0,%1,%2,%3}, [%4];" \
        : "=r"((r)[0]), "=r"((r)[1]), "=r"((r)[2]), "=r"((r)[3]) : "r"(addr))

#define MMA_BF16(c, a, b0, b1) \
    asm volatile("mma.sync.aligned.m16n8k16.row.col.f32.bf16.bf16.f32 " \
        "{%0,%1,%2,%3}, {%4,%5,%6,%7}, {%8,%9}, {%0,%1,%2,%3};" \
        : "+f"((c)[0]), "+f"((c)[1]), "+f"((c)[2]), "+f"((c)[3]) \
        : "r"((a)[0]), "r"((a)[1]), "r"((a)[2]), "r"((a)[3]), "r"(b0), "r"(b1))

// window-ordered column -> spatial patch index
__device__ __forceinline__ int spatial_col(int c) {
    int win = c / 49, pos = c - win * 49;
    int wy = win >> 3, wx = win & 7;
    int py = pos / 7,  px = pos - py * 7;
    return (wy * 7 + py) * CH + (wx * 7 + px);
}

// ------- fused shift + transpose + hi/lo convert -------
// out: xt_hi/xt_lo [NB][NPAD rows=c(window-ordered)][DD cols=d]
__global__ void shift_conv_kernel(const float* __restrict__ in,
                                  __nv_bfloat16* __restrict__ hi,
                                  __nv_bfloat16* __restrict__ lo) {
    long idx = (long)blockIdx.x * blockDim.x + threadIdx.x;
    if (idx >= (long)NB * PN * DD) return;
    int d  = (int)(idx % DD);
    int c  = (int)((idx / DD) % PN);
    int nb = (int)(idx / ((long)DD * PN));
    int win = c / 49, pos = c - win * 49;
    int wy = win >> 3, wx = win & 7;
    int py = pos / 7,  px = pos - py * 7;
    int i = wy * 7 + py, j = wx * 7 + px;
    int ch = d >> 4;
    int r = i * 4 + ((d >> 2) & 3), s = j * 4 + (d & 3);
    int rs = (r + PIX - 3) % PIX;
    int ss = (s + PIX - 3) % PIX;
    int dp = (ch << 4) + ((rs & 3) << 2) + (ss & 3);
    int pp = (rs >> 2) * CH + (ss >> 2);
    float x = in[((long)nb * DD + dp) * PN + pp];
    __nv_bfloat16 h = __float2bfloat16(x);
    long o = ((long)nb * NPAD + c) * DD + d;
    hi[o] = h;
    lo[o] = __float2bfloat16(x - __bfloat162float(h));
}

// ------------- weight conversion -------------------
__global__ void convert_weights(const float* __restrict__ Wk, const float* __restrict__ Wq,
                                const float* __restrict__ Wv, const float* __restrict__ bk,
                                const float* __restrict__ bq, const float* __restrict__ bv,
                                const float* __restrict__ Wo) {
    const long NW = 6144L * 256, NO = 256L * 2048;
    long i = (long)blockIdx.x * blockDim.x + threadIdx.x;
    if (i < NW) {
        int row = (int)(i >> 8), col = (int)(i & 255);
        const float* src = (row < 2048) ? Wk : ((row < 4096) ? Wq : Wv);
        float x = src[(long)(row & 2047) * 256 + col];
        __nv_bfloat16 h = __float2bfloat16(x);
        g_Wc_hi[i] = h;
        g_Wc_lo[i] = __float2bfloat16(x - __bfloat162float(h));
    } else if (i < NW + NO) {
        long j = i - NW;
        float x = Wo[j];
        __nv_bfloat16 h = __float2bfloat16(x);
        g_Wo_hi[j] = h;
        g_Wo_lo[j] = __float2bfloat16(x - __bfloat162float(h));
    } else if (i < NW + NO + 6144) {
        int r = (int)(i - NW - NO);
        const float* sb = (r < 2048) ? bk : ((r < 4096) ? bq : bv);
        g_bias_c[r] = sb[r & 2047];
    }
}

// ------------- HMMA bf16x3 GEMM --------------------
// 3-stage cp.async pipeline, one barrier per k-tile.
#define TSTRIDE 40                       // halves per smem row (32 + 8 pad)
#define TILE_HALVES (128 * TSTRIDE)      // 5120
#define STAGE_HALVES (4 * TILE_HALVES)   // 20480
#define GEMM_SMEM (3 * STAGE_HALVES * 2) // 122880 bytes

__global__ __launch_bounds__(256, 1) void gemm_kernel(
    const __nv_bfloat16* __restrict__ Ahi, const __nv_bfloat16* __restrict__ Alo,
    const __nv_bfloat16* __restrict__ Bhi, const __nv_bfloat16* __restrict__ Blo,
    const float* __restrict__ bias, float* __restrict__ Cbase,
    int K, long bStride, int mode)
{
    extern __shared__ __nv_bfloat16 sh[];
    const int tid = threadIdx.x;
    const int lane = tid & 31;
    const int wid = tid >> 5;
    const int wm = wid & 3;
    const int wn = wid >> 2;
    const int z  = blockIdx.z;
    const int m0g = blockIdx.y * 128;
    const int n0g = blockIdx.x * 128;
    const int T = K >> 5;

    const __nv_bfloat16* srcs[4];
    srcs[0] = Ahi + (long)m0g * K;
    srcs[1] = Alo + (long)m0g * K;
    srcs[2] = Bhi + (long)z * bStride + (long)n0g * K;
    srcs[3] = Blo + (long)z * bStride + (long)n0g * K;
    float* C = Cbase + ((mode == 0) ? (long)z * 3 * BATCH_QKV : (long)z * BATCH_X);

    const uint32_t smu = smem_u32(sh);
    const int ldr0 = tid >> 2;
    const int ldc0 = (tid & 3) << 3;

    float acc[2][8][4];
#pragma unroll
    for (int a = 0; a < 2; a++)
#pragma unroll
        for (int b = 0; b < 8; b++)
#pragma unroll
            for (int cc = 0; cc < 4; cc++) acc[a][b][cc] = 0.f;

    const int a_r = wm * 32 + ((lane >> 3) & 1) * 8 + (lane & 7);
    const int a_c = (lane >> 4) * 8;
    const int b_r = wn * 64 + (lane >> 4) * 8 + (lane & 7);
    const int b_c = ((lane >> 3) & 1) * 8;

    // ---- prologue: stages 0,1 ----
#pragma unroll
    for (int s = 0; s < 2; s++) {
#pragma unroll
        for (int tile = 0; tile < 4; tile++) {
#pragma unroll
            for (int j = 0; j < 2; j++) {
                int r = ldr0 + j * 64;
                uint32_t dst = smu +
                    (s * STAGE_HALVES + tile * TILE_HALVES + r * TSTRIDE + ldc0) * 2;
                CP16(dst, srcs[tile] + (long)r * K + s * 32 + ldc0);
            }
        }
        CP_COMMIT();
    }

    int cb = 0;      // compute buffer
    int ib = 2;      // issue buffer
    for (int t = 0; t < T; t++) {
        if (t + 1 < T) { CP_WAIT(1); } else { CP_WAIT(0); }
        __syncthreads();

        if (t + 2 < T) {
#pragma unroll
            for (int tile = 0; tile < 4; tile++) {
#pragma unroll
                for (int j = 0; j < 2; j++) {
                    int r = ldr0 + j * 64;
                    uint32_t dst = smu +
                        (ib * STAGE_HALVES + tile * TILE_HALVES + r * TSTRIDE + ldc0) * 2;
                    CP16(dst, srcs[tile] + (long)r * K + (t + 2) * 32 + ldc0);
                }
            }
            CP_COMMIT();
            ib++; if (ib == 3) ib = 0;
        }

        const uint32_t sb = smu + (cb * STAGE_HALVES) * 2;
        cb++; if (cb == 3) cb = 0;
        const uint32_t sAh = sb;
        const uint32_t sAl = sb + TILE_HALVES * 2;
        const uint32_t sBh = sb + 2 * TILE_HALVES * 2;
        const uint32_t sBl = sb + 3 * TILE_HALVES * 2;

#pragma unroll
        for (int k16 = 0; k16 < 2; k16++) {
            uint32_t ah[2][4], al[2][4];
#pragma unroll
            for (int mt = 0; mt < 2; mt++) {
                uint32_t off = ((a_r + mt * 16) * TSTRIDE + a_c + k16 * 16) * 2;
                LDSM4(ah[mt], sAh + off);
                LDSM4(al[mt], sAl + off);
            }
#pragma unroll
            for (int nt2 = 0; nt2 < 4; nt2++) {
                uint32_t bh[4], bl[4];
                uint32_t off = ((b_r + nt2 * 16) * TSTRIDE + b_c + k16 * 16) * 2;
                LDSM4(bh, sBh + off);
                LDSM4(bl, sBl + off);
#pragma unroll
                for (int mt = 0; mt < 2; mt++) {
#pragma unroll
                    for (int sn = 0; sn < 2; sn++) {
                        float* cc = acc[mt][nt2 * 2 + sn];
                        MMA_BF16(cc, ah[mt], bh[sn * 2], bh[sn * 2 + 1]);
                        MMA_BF16(cc, ah[mt], bl[sn * 2], bl[sn * 2 + 1]);
                        MMA_BF16(cc, al[mt], bh[sn * 2], bh[sn * 2 + 1]);
                    }
                }
            }
        }
    }

    // ---- epilogue: direct global stores ----
#pragma unroll
    for (int mt = 0; mt < 2; mt++) {
#pragma unroll
        for (int half = 0; half < 2; half++) {
            int m = m0g + wm * 32 + mt * 16 + (lane >> 2) + half * 8;
            float bb = bias[m];
            long rowoff;
            if (mode == 0)
                rowoff = (long)(m >> 11) * BATCH_QKV + (long)(m & 2047) * PN;
            else
                rowoff = (long)m * PN;
#pragma unroll
            for (int nt = 0; nt < 8; nt++) {
                int n = n0g + wn * 64 + nt * 8 + ((lane & 3) << 1);
                if (n >= PN) continue;
                float v0 = acc[mt][nt][half * 2 + 0] + bb;
                float v1 = acc[mt][nt][half * 2 + 1] + bb;
                if (mode == 0) {
                    float2 st; st.x = v0; st.y = v1;
                    *(float2*)&C[rowoff + n] = st;
                } else {
                    C[rowoff + spatial_col(n)] = v0;
                    C[rowoff + spatial_col(n + 1)] = v1;
                }
            }
        }
    }
}

// ---------------- attention kernel ------------------
// Emits at_hi/at_lo ([row = nb*NPAD + g*49+q][col = h*256+d], bf16) directly.
#define ATTN_SMEM_FLOATS (17408 + 2548 + 169 + 49)
#define ATTN_SMEM_BYTES  (ATTN_SMEM_FLOATS * 4)

__global__ __launch_bounds__(256) void attn_kernel(const float* __restrict__ qkv,
                                                   const float* __restrict__ rel_code,
                                                   __nv_bfloat16* __restrict__ at_hi,
                                                   __nv_bfloat16* __restrict__ at_lo) {
    extern __shared__ float sm[];
    float* buf   = sm;
    float* Ssm   = sm + 17408;
    float* rel_s = sm + 17408 + 2548;
    int*   fm_s  = (int*)(rel_s + 169);

    const int g  = blockIdx.x;
    const int h  = blockIdx.y;
    const int nb = blockIdx.z;
    const int tid = threadIdx.x;

    const long baseK = ((long)nb * 3 + 0) * BATCH_QKV + (long)(h * DD) * PN + g * 49;
    const long baseQ = baseK + BATCH_QKV;
    const long baseV = baseK + 2 * BATCH_QKV;

    if (tid < 169) rel_s[tid] = rel_code[tid * HEADS + h];
    if (tid < P) {
        int gy = g >> 3, gx = g & 7;
        int ty = tid / 7, tx = tid - ty * 7;
        int rr = gy * 7 + ty, cc = gx * 7 + tx;
        int ry = (rr < 49) ? 0 : ((rr < 53) ? 1 : 2);
        int rx = (cc < 49) ? 0 : ((cc < 53) ? 1 : 2);
        fm_s[tid] = ry * 3 + rx;
    }
    __syncthreads();

    const int txc = tid & 15, tyc = tid >> 4;
    float acc[4][4];
#pragma unroll
    for (int i = 0; i < 4; i++)
#pragma unroll
        for (int j = 0; j < 4; j++) acc[i][j] = 0.f;

    for (int c = 0; c < 2; c++) {
        for (int i = tid; i < 128 * 64; i += 256) {
            int d = i >> 6;
            int p = i & 63;
            float kv = 0.f, qv = 0.f;
            if (p < P) {
                long off = (long)(c * 128 + d) * PN + p;
                kv = qkv[baseK + off];
                qv = qkv[baseQ + off];
            }
            buf[d * 68 + p]        = kv;
            buf[8704 + d * 68 + p] = qv;
        }
        __syncthreads();
#pragma unroll 4
        for (int d = 0; d < 128; d++) {
            float4 kf = *(const float4*)&buf[d * 68 + txc * 4];
            float4 qf = *(const float4*)&buf[8704 + d * 68 + tyc * 4];
            float kk[4] = {kf.x, kf.y, kf.z, kf.w};
            float qq[4] = {qf.x, qf.y, qf.z, qf.w};
#pragma unroll
            for (int i = 0; i < 4; i++)
#pragma unroll
                for (int j = 0; j < 4; j++)
                    acc[i][j] += kk[i] * qq[j];
        }
        __syncthreads();
    }

    const float scale = 0.0625f;
#pragma unroll
    for (int i = 0; i < 4; i++) {
        int p = txc * 4 + i;
        if (p >= P) continue;
        int py = p / WS, px = p % WS;
        int fmp = fm_s[p];
#pragma unroll
        for (int j = 0; j < 4; j++) {
            int q = tyc * 4 + j;
            if (q >= P) continue;
            int qy = q / WS, qx = q % WS;
            float r = rel_s[(py - qy + 6) + 13 * (px - qx + 6)];
            float mval = (fmp == fm_s[q]) ? 0.f : -100.f;
            Ssm[p * 52 + q] = acc[i][j] * scale + mval + r;
        }
    }
    __syncthreads();

    if (tid < P) {
        float m = -1e30f;
        for (int p = 0; p < P; p++) m = fmaxf(m, Ssm[p * 52 + tid]);
        float s = 0.f;
        for (int p = 0; p < P; p++) {
            float e = __expf(Ssm[p * 52 + tid] - m);
            Ssm[p * 52 + tid] = e;
            s += e;
        }
        float inv = 1.f / s;
        for (int p = 0; p < P; p++) Ssm[p * 52 + tid] *= inv;
    }
    __syncthreads();

    for (int i = tid; i < 256 * 64; i += 256) {
        int d = i >> 6;
        int p = i & 63;
        float vv = 0.f;
        if (p < P) vv = qkv[baseV + (long)d * PN + p];
        buf[d * 68 + p] = vv;
    }
    __syncthreads();

    const int d = tid;
    float v[P];
#pragma unroll
    for (int p = 0; p < P; p++) v[p] = buf[d * 68 + p];
    __syncthreads();

    // stage output as buf[q*256 + d] (conflict-free both directions)
    for (int q0 = 0; q0 < 48; q0 += 4) {
        float a0 = 0.f, a1 = 0.f, a2 = 0.f, a3 = 0.f;
#pragma unroll
        for (int p = 0; p < P; p++) {
            float4 w = *(const float4*)&Ssm[p * 52 + q0];
            a0 += v[p] * w.x;
            a1 += v[p] * w.y;
            a2 += v[p] * w.z;
            a3 += v[p] * w.w;
        }
        buf[(q0 + 0) * 256 + d] = a0;
        buf[(q0 + 1) * 256 + d] = a1;
        buf[(q0 + 2) * 256 + d] = a2;
        buf[(q0 + 3) * 256 + d] = a3;
    }
    {
        float a = 0.f;
#pragma unroll
        for (int p = 0; p < P; p++) a += v[p] * Ssm[p * 52 + 48];
        buf[48 * 256 + d] = a;
    }
    __syncthreads();

    // coalesced bf16 hi/lo write-out (transposed layout for outproj)
    const long rowbase = (long)nb * NPAD + g * 49;
    for (int q = 0; q < P; q++) {
        float vv = buf[q * 256 + tid];
        __nv_bfloat16 hh = __float2bfloat16(vv);
        long o = (rowbase + q) * HD + h * DD + tid;
        at_hi[o] = hh;
        at_lo[o] = __float2bfloat16(vv - __bfloat162float(hh));
    }
}

// ---------------- launch -----------------------------
extern "C" void kernel_launch(void* const* d_in, const int* in_sizes, int n_in,
                              void* d_out, int out_size) {
    const float* inputs = (const float*)d_in[0];
    const float* Wk = (const float*)d_in[1];
    const float* bk = (const float*)d_in[2];
    const float* Wq = (const float*)d_in[3];
    const float* bq = (const float*)d_in[4];
    const float* Wv = (const float*)d_in[5];
    const float* bv = (const float*)d_in[6];
    const float* Wo = (const float*)d_in[7];
    const float* bo = (const float*)d_in[8];
    const float* rel = (const float*)d_in[9];
    float* out = (float*)d_out;

    float *qkv, *bias_c;
    __nv_bfloat16 *Wc_hi, *Wc_lo, *Wo_hi, *Wo_lo, *xt_hi, *xt_lo, *at_hi, *at_lo;
    cudaGetSymbolAddress((void**)&qkv, g_qkv);
    cudaGetSymbolAddress((void**)&bias_c, g_bias_c);
    cudaGetSymbolAddress((void**)&Wc_hi, g_Wc_hi);
    cudaGetSymbolAddress((void**)&Wc_lo, g_Wc_lo);
    cudaGetSymbolAddress((void**)&Wo_hi, g_Wo_hi);
    cudaGetSymbolAddress((void**)&Wo_lo, g_Wo_lo);
    cudaGetSymbolAddress((void**)&xt_hi, g_xt_hi);
    cudaGetSymbolAddress((void**)&xt_lo, g_xt_lo);
    cudaGetSymbolAddress((void**)&at_hi, g_at_hi);
    cudaGetSymbolAddress((void**)&at_lo, g_at_lo);

    cudaFuncSetAttribute(attn_kernel, cudaFuncAttributeMaxDynamicSharedMemorySize,
                         ATTN_SMEM_BYTES);
    cudaFuncSetAttribute(gemm_kernel, cudaFuncAttributeMaxDynamicSharedMemorySize,
                         GEMM_SMEM);

    {
        long total = (long)NB * PN * DD;
        shift_conv_kernel<<<(int)((total + 255) / 256), 256>>>(inputs, xt_hi, xt_lo);
    }
    {
        long total = 6144L * 256 + 256L * 2048 + 6144;
        convert_weights<<<(int)((total + 255) / 256), 256>>>(Wk, Wq, Wv, bk, bq, bv, Wo);
    }
    gemm_kernel<<<dim3(25, 48, 8), 256, GEMM_SMEM>>>(Wc_hi, Wc_lo, xt_hi, xt_lo,
                                                     bias_c, qkv, 256, (long)NPAD * DD, 0);
    attn_kernel<<<dim3(WIN, HEADS, NB), 256, ATTN_SMEM_BYTES>>>(qkv, rel, at_hi, at_lo);
    gemm_kernel<<<dim3(25, 2, 8), 256, GEMM_SMEM>>>(Wo_hi, Wo_lo, at_hi, at_lo,
                                                    bo, out, 2048, (long)NPAD * HD, 1);
}